// round 1
// baseline (speedup 1.0000x reference)
#include <cuda_runtime.h>

// Problem constants (B=32, S=4096, 22 joints, 20 output joints)
#define FRAMES   (32 * 4096)
#define TPB      256
#define NBLK     (FRAMES / TPB)   // 512

__device__ float g_partial[NBLK];

struct V3 { float x, y, z; };
struct M3 { V3 c0, c1, c2; };   // columns

__device__ __forceinline__ V3 mk3(float x, float y, float z) { V3 v; v.x=x; v.y=y; v.z=z; return v; }
__device__ __forceinline__ V3 v_add(V3 a, V3 b) { return mk3(a.x+b.x, a.y+b.y, a.z+b.z); }

__device__ __forceinline__ V3 matvec(const M3& m, V3 v) {
    return mk3(fmaf(m.c0.x, v.x, fmaf(m.c1.x, v.y, m.c2.x * v.z)),
               fmaf(m.c0.y, v.x, fmaf(m.c1.y, v.y, m.c2.y * v.z)),
               fmaf(m.c0.z, v.x, fmaf(m.c1.z, v.y, m.c2.z * v.z)));
}
__device__ __forceinline__ M3 matmul(const M3& a, const M3& b) {
    M3 r; r.c0 = matvec(a, b.c0); r.c1 = matvec(a, b.c1); r.c2 = matvec(a, b.c2); return r;
}

// 6D continuous rotation rep -> 3x3 matrix (columns b1,b2,b3).
// Matches: b1 = a1/max(|a1|,1e-12); b2 = normalize(a2 - (b1.a2) b1); b3 = b1 x b2
__device__ __forceinline__ M3 conv6d(const float* __restrict__ d) {
    float2 u = __ldg((const float2*)(d + 0));
    float2 v = __ldg((const float2*)(d + 2));
    float2 w = __ldg((const float2*)(d + 4));
    V3 a1 = mk3(u.x, u.y, v.x);
    V3 a2 = mk3(v.y, w.x, w.y);

    float n1 = fmaf(a1.x, a1.x, fmaf(a1.y, a1.y, a1.z * a1.z));
    float i1 = rsqrtf(fmaxf(n1, 1e-24f));
    V3 b1 = mk3(a1.x * i1, a1.y * i1, a1.z * i1);

    float dp = fmaf(b1.x, a2.x, fmaf(b1.y, a2.y, b1.z * a2.z));
    V3 t = mk3(fmaf(-dp, b1.x, a2.x), fmaf(-dp, b1.y, a2.y), fmaf(-dp, b1.z, a2.z));
    float n2 = fmaf(t.x, t.x, fmaf(t.y, t.y, t.z * t.z));
    float i2 = rsqrtf(fmaxf(n2, 1e-24f));
    V3 b2 = mk3(t.x * i2, t.y * i2, t.z * i2);

    V3 b3 = mk3(b1.y * b2.z - b1.z * b2.y,
                b1.z * b2.x - b1.x * b2.z,
                b1.x * b2.y - b1.y * b2.x);
    M3 m; m.c0 = b1; m.c1 = b2; m.c2 = b3; return m;
}

__device__ __forceinline__ float dist_to_pred(const float* __restrict__ p, int k, V3 g) {
    float dx = __ldg(p + 3 * k + 0) - g.x;
    float dy = __ldg(p + 3 * k + 1) - g.y;
    float dz = __ldg(p + 3 * k + 2) - g.z;
    return sqrtf(fmaf(dx, dx, fmaf(dy, dy, dz * dz)));
}

__global__ void __launch_bounds__(TPB)
fk_mpjpe_kernel(const float* __restrict__ pred,   // [FRAMES, 20, 3]
                const float* __restrict__ rot,    // [FRAMES, 22, 6]
                const float* __restrict__ off)    // [22, 3]
{
    __shared__ float soff[66];
    if (threadIdx.x < 66) soff[threadIdx.x] = off[threadIdx.x];
    __syncthreads();

    int fid = blockIdx.x * TPB + threadIdx.x;
    const float* rr = rot  + (size_t)fid * 132;
    const float* pp = pred + (size_t)fid * 60;

    #define OFF3(i) mk3(soff[3*(i)], soff[3*(i)+1], soff[3*(i)+2])

    float acc = 0.f;

    // ---- chain: 1(identity) -> 4 -> 7 -> 10 ----
    V3 pos1 = OFF3(1);                       // g_rot[0]=I, g_rot[1]=I
    M3 G4 = conv6d(rr + 4 * 6);              // g_rot[4] = I @ rot[4]
    V3 pos4 = v_add(pos1, OFF3(4));          acc += dist_to_pred(pp, 2, pos4);
    M3 G7 = matmul(G4, conv6d(rr + 7 * 6));
    V3 pos7 = v_add(pos4, matvec(G4, OFF3(7)));   acc += dist_to_pred(pp, 5, pos7);
    V3 pos10 = v_add(pos7, matvec(G7, OFF3(10))); acc += dist_to_pred(pp, 8, pos10);

    // ---- chain: 2 -> 5 -> 8 -> 11 ----
    M3 G2 = conv6d(rr + 2 * 6);
    V3 pos2 = OFF3(2);                       acc += dist_to_pred(pp, 0, pos2);
    M3 G5 = matmul(G2, conv6d(rr + 5 * 6));
    V3 pos5 = v_add(pos2, matvec(G2, OFF3(5)));   acc += dist_to_pred(pp, 3, pos5);
    M3 G8 = matmul(G5, conv6d(rr + 8 * 6));
    V3 pos8 = v_add(pos5, matvec(G5, OFF3(8)));   acc += dist_to_pred(pp, 6, pos8);
    V3 pos11 = v_add(pos8, matvec(G8, OFF3(11))); acc += dist_to_pred(pp, 9, pos11);

    // ---- chain: 3 -> 6 -> 9, branches {12->15, 13->16->18->20, 14->17->19->21} ----
    M3 G3 = conv6d(rr + 3 * 6);
    V3 pos3 = OFF3(3);                       acc += dist_to_pred(pp, 1, pos3);
    M3 G6 = matmul(G3, conv6d(rr + 6 * 6));
    V3 pos6 = v_add(pos3, matvec(G3, OFF3(6)));   acc += dist_to_pred(pp, 4, pos6);
    M3 G9 = matmul(G6, conv6d(rr + 9 * 6));
    V3 pos9 = v_add(pos6, matvec(G6, OFF3(9)));   acc += dist_to_pred(pp, 7, pos9);

    // 12 -> 15
    M3 G12 = matmul(G9, conv6d(rr + 12 * 6));
    V3 pos12 = v_add(pos9, matvec(G9, OFF3(12)));   acc += dist_to_pred(pp, 10, pos12);
    V3 pos15 = v_add(pos12, matvec(G12, OFF3(15))); acc += dist_to_pred(pp, 13, pos15);

    // 13 -> 16 -> 18 -> 20
    M3 G13 = matmul(G9, conv6d(rr + 13 * 6));
    V3 pos13 = v_add(pos9, matvec(G9, OFF3(13)));   acc += dist_to_pred(pp, 11, pos13);
    M3 G16 = matmul(G13, conv6d(rr + 16 * 6));
    V3 pos16 = v_add(pos13, matvec(G13, OFF3(16))); acc += dist_to_pred(pp, 14, pos16);
    M3 G18 = matmul(G16, conv6d(rr + 18 * 6));
    V3 pos18 = v_add(pos16, matvec(G16, OFF3(18))); acc += dist_to_pred(pp, 16, pos18);
    V3 pos20 = v_add(pos18, matvec(G18, OFF3(20))); acc += dist_to_pred(pp, 18, pos20);

    // 14 -> 17 -> 19 -> 21
    M3 G14 = matmul(G9, conv6d(rr + 14 * 6));
    V3 pos14 = v_add(pos9, matvec(G9, OFF3(14)));   acc += dist_to_pred(pp, 12, pos14);
    M3 G17 = matmul(G14, conv6d(rr + 17 * 6));
    V3 pos17 = v_add(pos14, matvec(G14, OFF3(17))); acc += dist_to_pred(pp, 15, pos17);
    M3 G19 = matmul(G17, conv6d(rr + 19 * 6));
    V3 pos19 = v_add(pos17, matvec(G17, OFF3(19))); acc += dist_to_pred(pp, 17, pos19);
    V3 pos21 = v_add(pos19, matvec(G19, OFF3(21))); acc += dist_to_pred(pp, 19, pos21);

    #undef OFF3

    // ---- deterministic block reduction ----
    #pragma unroll
    for (int o = 16; o > 0; o >>= 1)
        acc += __shfl_down_sync(0xffffffffu, acc, o);

    __shared__ float wsum[TPB / 32];
    int lane = threadIdx.x & 31, wid = threadIdx.x >> 5;
    if (lane == 0) wsum[wid] = acc;
    __syncthreads();
    if (threadIdx.x == 0) {
        float s = 0.f;
        #pragma unroll
        for (int i = 0; i < TPB / 32; i++) s += wsum[i];
        g_partial[blockIdx.x] = s;
    }
}

__global__ void reduce_kernel(float* __restrict__ out) {
    __shared__ float sh[NBLK];
    int t = threadIdx.x;
    sh[t] = g_partial[t];
    __syncthreads();
    #pragma unroll
    for (int s = NBLK / 2; s > 0; s >>= 1) {
        if (t < s) sh[t] += sh[t + s];
        __syncthreads();
    }
    if (t == 0) out[0] = sh[0] * (1000.0f / (float)(FRAMES * 20));
}

extern "C" void kernel_launch(void* const* d_in, const int* in_sizes, int n_in,
                              void* d_out, int out_size) {
    const float* pred = (const float*)d_in[0];   // pred_pos [32,4096,20,3]
    const float* rot  = (const float*)d_in[1];   // gt_rot   [32,4096,22,6]
    const float* off  = (const float*)d_in[2];   // offsets  [22,3]
    float* out = (float*)d_out;

    fk_mpjpe_kernel<<<NBLK, TPB>>>(pred, rot, off);
    reduce_kernel<<<1, NBLK>>>(out);
}

// round 2
// speedup vs baseline: 1.2267x; 1.2267x over previous
#include <cuda_runtime.h>

// Problem constants (B=32, S=4096, 22 joints, 20 output joints)
#define FRAMES   (32 * 4096)
#define TPB      128
#define NBLK     (FRAMES / TPB)   // 1024

__device__ float    g_partial[NBLK];
__device__ unsigned g_count = 0;

struct V3 { float x, y, z; };
struct M3 { V3 c0, c1, c2; };   // columns

__device__ __forceinline__ V3 mk3(float x, float y, float z) { V3 v; v.x=x; v.y=y; v.z=z; return v; }
__device__ __forceinline__ V3 v_add(V3 a, V3 b) { return mk3(a.x+b.x, a.y+b.y, a.z+b.z); }

__device__ __forceinline__ V3 matvec(const M3& m, V3 v) {
    return mk3(fmaf(m.c0.x, v.x, fmaf(m.c1.x, v.y, m.c2.x * v.z)),
               fmaf(m.c0.y, v.x, fmaf(m.c1.y, v.y, m.c2.y * v.z)),
               fmaf(m.c0.z, v.x, fmaf(m.c1.z, v.y, m.c2.z * v.z)));
}
__device__ __forceinline__ M3 matmul(const M3& a, const M3& b) {
    M3 r; r.c0 = matvec(a, b.c0); r.c1 = matvec(a, b.c1); r.c2 = matvec(a, b.c2); return r;
}

// 6D continuous rotation rep -> 3x3 matrix (columns b1,b2,b3).
__device__ __forceinline__ M3 conv6d(V3 a1, V3 a2) {
    float n1 = fmaf(a1.x, a1.x, fmaf(a1.y, a1.y, a1.z * a1.z));
    float i1 = rsqrtf(fmaxf(n1, 1e-24f));
    V3 b1 = mk3(a1.x * i1, a1.y * i1, a1.z * i1);

    float dp = fmaf(b1.x, a2.x, fmaf(b1.y, a2.y, b1.z * a2.z));
    V3 t = mk3(fmaf(-dp, b1.x, a2.x), fmaf(-dp, b1.y, a2.y), fmaf(-dp, b1.z, a2.z));
    float n2 = fmaf(t.x, t.x, fmaf(t.y, t.y, t.z * t.z));
    float i2 = rsqrtf(fmaxf(n2, 1e-24f));
    V3 b2 = mk3(t.x * i2, t.y * i2, t.z * i2);

    V3 b3 = mk3(b1.y * b2.z - b1.z * b2.y,
                b1.z * b2.x - b1.x * b2.z,
                b1.x * b2.y - b1.y * b2.x);
    M3 m; m.c0 = b1; m.c1 = b2; m.c2 = b3; return m;
}

// two alignment forms of a 6-float span inside consecutive float4s
__device__ __forceinline__ M3 convA(float4 p, float4 q) {   // span starts at comp 0
    return conv6d(mk3(p.x, p.y, p.z), mk3(p.w, q.x, q.y));
}
__device__ __forceinline__ M3 convB(float4 p, float4 q) {   // span starts at comp 2
    return conv6d(mk3(p.z, p.w, q.x), mk3(q.y, q.z, q.w));
}

__device__ __forceinline__ float dst(V3 p, V3 g) {
    float dx = p.x - g.x, dy = p.y - g.y, dz = p.z - g.z;
    return sqrtf(fmaf(dx, dx, fmaf(dy, dy, dz * dz)));
}

__global__ void __launch_bounds__(TPB)
fk_mpjpe_kernel(const float* __restrict__ pred,   // [FRAMES, 20, 3]
                const float* __restrict__ rot,    // [FRAMES, 22, 6]
                const float* __restrict__ off,    // [22, 3]
                float* __restrict__ out)
{
    __shared__ float soff[66];
    if (threadIdx.x < 66) soff[threadIdx.x] = off[threadIdx.x];
    __syncthreads();

    int fid = blockIdx.x * TPB + threadIdx.x;
    const float4* R = (const float4*)(rot  + (size_t)fid * 132);  // 33 vec4 per frame
    const float4* P = (const float4*)(pred + (size_t)fid * 60);   // 15 vec4 per frame

    #define OFF3(i) mk3(soff[3*(i)], soff[3*(i)+1], soff[3*(i)+2])

    // ---- rot loads (only the 23 used float4 words of 33) ----
    float4 q3  = __ldg(R+3),  q4  = __ldg(R+4),  q5  = __ldg(R+5);
    float4 q6  = __ldg(R+6),  q7  = __ldg(R+7),  q8  = __ldg(R+8);
    float4 q9  = __ldg(R+9),  q10 = __ldg(R+10), q11 = __ldg(R+11);
    float4 q12 = __ldg(R+12), q13 = __ldg(R+13), q14 = __ldg(R+14);
    float4 q18 = __ldg(R+18), q19 = __ldg(R+19), q20 = __ldg(R+20);
    float4 q21 = __ldg(R+21), q22 = __ldg(R+22);
    float4 q24 = __ldg(R+24), q25 = __ldg(R+25), q26 = __ldg(R+26);
    float4 q27 = __ldg(R+27), q28 = __ldg(R+28), q29 = __ldg(R+29);

    // ---- pred loads (all 15 float4 words) ----
    float4 p0  = __ldg(P+0),  p1  = __ldg(P+1),  p2  = __ldg(P+2);
    float4 p3  = __ldg(P+3),  p4  = __ldg(P+4),  p5  = __ldg(P+5);
    float4 p6  = __ldg(P+6),  p7  = __ldg(P+7),  p8  = __ldg(P+8);
    float4 p9  = __ldg(P+9),  p10 = __ldg(P+10), p11 = __ldg(P+11);
    float4 p12 = __ldg(P+12), p13 = __ldg(P+13), p14 = __ldg(P+14);

    float acc = 0.f;

    // ---- chain: 1(identity) -> 4 -> 7 -> 10 ----
    {
        M3 G4 = convA(q6, q7);                       // joint 4 (e=24)
        V3 pos4 = v_add(OFF3(1), OFF3(4));
        acc += dst(mk3(p1.z, p1.w, p2.x), pos4);                 // k=2
        M3 G7 = matmul(G4, convB(q10, q11));         // joint 7 (e=42)
        V3 pos7 = v_add(pos4, matvec(G4, OFF3(7)));
        acc += dst(mk3(p3.w, p4.x, p4.y), pos7);                 // k=5
        V3 pos10 = v_add(pos7, matvec(G7, OFF3(10)));
        acc += dst(mk3(p6.x, p6.y, p6.z), pos10);                // k=8
    }

    // ---- chain: 2 -> 5 -> 8 -> 11 ----
    {
        M3 G2 = convA(q3, q4);                       // joint 2 (e=12)
        V3 pos2 = OFF3(2);
        acc += dst(mk3(p0.x, p0.y, p0.z), pos2);                 // k=0
        M3 G5 = matmul(G2, convB(q7, q8));           // joint 5 (e=30)
        V3 pos5 = v_add(pos2, matvec(G2, OFF3(5)));
        acc += dst(mk3(p2.y, p2.z, p2.w), pos5);                 // k=3
        M3 G8 = matmul(G5, convA(q12, q13));         // joint 8 (e=48)
        V3 pos8 = v_add(pos5, matvec(G5, OFF3(8)));
        acc += dst(mk3(p4.z, p4.w, p5.x), pos8);                 // k=6
        V3 pos11 = v_add(pos8, matvec(G8, OFF3(11)));
        acc += dst(mk3(p6.w, p7.x, p7.y), pos11);                // k=9
    }

    // ---- chain: 3 -> 6 -> 9, branches {12->15, 13->16->18->20, 14->17->19->21} ----
    M3 G3 = convB(q4, q5);                           // joint 3 (e=18)
    V3 pos3 = OFF3(3);
    acc += dst(mk3(p0.w, p1.x, p1.y), pos3);                     // k=1
    M3 G6 = matmul(G3, convA(q9, q10));              // joint 6 (e=36)
    V3 pos6 = v_add(pos3, matvec(G3, OFF3(6)));
    acc += dst(mk3(p3.x, p3.y, p3.z), pos6);                     // k=4
    M3 G9 = matmul(G6, convB(q13, q14));             // joint 9 (e=54)
    V3 pos9 = v_add(pos6, matvec(G6, OFF3(9)));
    acc += dst(mk3(p5.y, p5.z, p5.w), pos9);                     // k=7

    // 12 -> 15
    {
        M3 G12 = matmul(G9, convA(q18, q19));        // joint 12 (e=72)
        V3 pos12 = v_add(pos9, matvec(G9, OFF3(12)));
        acc += dst(mk3(p7.z, p7.w, p8.x), pos12);                // k=10
        V3 pos15 = v_add(pos12, matvec(G12, OFF3(15)));
        acc += dst(mk3(p9.w, p10.x, p10.y), pos15);              // k=13
    }

    // 13 -> 16 -> 18 -> 20
    {
        M3 G13 = matmul(G9, convB(q19, q20));        // joint 13 (e=78)
        V3 pos13 = v_add(pos9, matvec(G9, OFF3(13)));
        acc += dst(mk3(p8.y, p8.z, p8.w), pos13);                // k=11
        M3 G16 = matmul(G13, convA(q24, q25));       // joint 16 (e=96)
        V3 pos16 = v_add(pos13, matvec(G13, OFF3(16)));
        acc += dst(mk3(p10.z, p10.w, p11.x), pos16);             // k=14
        M3 G18 = matmul(G16, convA(q27, q28));       // joint 18 (e=108)
        V3 pos18 = v_add(pos16, matvec(G16, OFF3(18)));
        acc += dst(mk3(p12.x, p12.y, p12.z), pos18);             // k=16
        V3 pos20 = v_add(pos18, matvec(G18, OFF3(20)));
        acc += dst(mk3(p13.z, p13.w, p14.x), pos20);             // k=18
    }

    // 14 -> 17 -> 19 -> 21
    {
        M3 G14 = matmul(G9, convA(q21, q22));        // joint 14 (e=84)
        V3 pos14 = v_add(pos9, matvec(G9, OFF3(14)));
        acc += dst(mk3(p9.x, p9.y, p9.z), pos14);                // k=12
        M3 G17 = matmul(G14, convB(q25, q26));       // joint 17 (e=102)
        V3 pos17 = v_add(pos14, matvec(G14, OFF3(17)));
        acc += dst(mk3(p11.y, p11.z, p11.w), pos17);             // k=15
        M3 G19 = matmul(G17, convB(q28, q29));       // joint 19 (e=114)
        V3 pos19 = v_add(pos17, matvec(G17, OFF3(19)));
        acc += dst(mk3(p13.w, p14.x, p14.y), pos19);             // k=17
        V3 pos21 = v_add(pos19, matvec(G19, OFF3(21)));
        acc += dst(mk3(p14.y, p14.z, p14.w), pos21);             // k=19
    }

    #undef OFF3

    // ---- deterministic block reduction ----
    #pragma unroll
    for (int o = 16; o > 0; o >>= 1)
        acc += __shfl_down_sync(0xffffffffu, acc, o);

    __shared__ float wsum[TPB / 32];
    int lane = threadIdx.x & 31, wid = threadIdx.x >> 5;
    if (lane == 0) wsum[wid] = acc;
    __syncthreads();

    __shared__ bool is_last;
    if (threadIdx.x == 0) {
        float s = 0.f;
        #pragma unroll
        for (int i = 0; i < TPB / 32; i++) s += wsum[i];
        g_partial[blockIdx.x] = s;
        __threadfence();
        unsigned prev = atomicAdd(&g_count, 1u);
        is_last = (prev == NBLK - 1);
    }
    __syncthreads();

    // ---- last block folds all partials (fixed order -> deterministic) ----
    if (is_last) {
        int t = threadIdx.x;
        float s = 0.f;
        #pragma unroll
        for (int j = 0; j < NBLK / TPB; j++) {
            const float* addr = g_partial + t + j * TPB;
            float v;
            asm volatile("ld.global.cg.f32 %0, [%1];" : "=f"(v) : "l"(addr));
            s += v;
        }
        __shared__ float sh[TPB];
        sh[t] = s;
        __syncthreads();
        #pragma unroll
        for (int k = TPB / 2; k > 0; k >>= 1) {
            if (t < k) sh[t] += sh[t + k];
            __syncthreads();
        }
        if (t == 0) {
            out[0] = sh[0] * (1000.0f / (float)(FRAMES * 20));
            g_count = 0;   // reset for next graph replay
        }
    }
}

extern "C" void kernel_launch(void* const* d_in, const int* in_sizes, int n_in,
                              void* d_out, int out_size) {
    const float* pred = (const float*)d_in[0];   // pred_pos [32,4096,20,3]
    const float* rot  = (const float*)d_in[1];   // gt_rot   [32,4096,22,6]
    const float* off  = (const float*)d_in[2];   // offsets  [22,3]
    float* out = (float*)d_out;

    fk_mpjpe_kernel<<<NBLK, TPB>>>(pred, rot, off, out);
}

// round 3
// speedup vs baseline: 1.2458x; 1.0156x over previous
#include <cuda_runtime.h>

// Problem constants (B=32, S=4096, 22 joints, 20 output joints)
#define FRAMES   (32 * 4096)
#define TPB      128
#define NBLK     (FRAMES / TPB)   // 1024

__device__ float    g_partial[NBLK];
__device__ unsigned g_count = 0;

struct V3 { float x, y, z; };
struct M3 { V3 c0, c1, c2; };   // columns

__device__ __forceinline__ V3 mk3(float x, float y, float z) { V3 v; v.x=x; v.y=y; v.z=z; return v; }
__device__ __forceinline__ V3 v_add(V3 a, V3 b) { return mk3(a.x+b.x, a.y+b.y, a.z+b.z); }

__device__ __forceinline__ V3 matvec(const M3& m, V3 v) {
    return mk3(fmaf(m.c0.x, v.x, fmaf(m.c1.x, v.y, m.c2.x * v.z)),
               fmaf(m.c0.y, v.x, fmaf(m.c1.y, v.y, m.c2.y * v.z)),
               fmaf(m.c0.z, v.x, fmaf(m.c1.z, v.y, m.c2.z * v.z)));
}
__device__ __forceinline__ M3 matmul(const M3& a, const M3& b) {
    M3 r; r.c0 = matvec(a, b.c0); r.c1 = matvec(a, b.c1); r.c2 = matvec(a, b.c2); return r;
}

// 6D continuous rotation rep -> 3x3 matrix (columns b1,b2,b3).
__device__ __forceinline__ M3 conv6d(V3 a1, V3 a2) {
    float n1 = fmaf(a1.x, a1.x, fmaf(a1.y, a1.y, a1.z * a1.z));
    float i1 = rsqrtf(fmaxf(n1, 1e-24f));
    V3 b1 = mk3(a1.x * i1, a1.y * i1, a1.z * i1);

    float dp = fmaf(b1.x, a2.x, fmaf(b1.y, a2.y, b1.z * a2.z));
    V3 t = mk3(fmaf(-dp, b1.x, a2.x), fmaf(-dp, b1.y, a2.y), fmaf(-dp, b1.z, a2.z));
    float n2 = fmaf(t.x, t.x, fmaf(t.y, t.y, t.z * t.z));
    float i2 = rsqrtf(fmaxf(n2, 1e-24f));
    V3 b2 = mk3(t.x * i2, t.y * i2, t.z * i2);

    V3 b3 = mk3(b1.y * b2.z - b1.z * b2.y,
                b1.z * b2.x - b1.x * b2.z,
                b1.x * b2.y - b1.y * b2.x);
    M3 m; m.c0 = b1; m.c1 = b2; m.c2 = b3; return m;
}

// two alignment forms of a 6-float span inside consecutive float4s
__device__ __forceinline__ M3 convA(float4 p, float4 q) {   // span starts at comp 0
    return conv6d(mk3(p.x, p.y, p.z), mk3(p.w, q.x, q.y));
}
__device__ __forceinline__ M3 convB(float4 p, float4 q) {   // span starts at comp 2
    return conv6d(mk3(p.z, p.w, q.x), mk3(q.y, q.z, q.w));
}

__device__ __forceinline__ float dst(V3 p, V3 g) {
    float dx = p.x - g.x, dy = p.y - g.y, dz = p.z - g.z;
    return sqrtf(fmaf(dx, dx, fmaf(dy, dy, dz * dz)));
}

// Cap registers at ~102 (5 CTAs/SM -> 20 warps) to fix latency-bound occupancy.
__global__ void __launch_bounds__(TPB, 5)
fk_mpjpe_kernel(const float* __restrict__ pred,   // [FRAMES, 20, 3]
                const float* __restrict__ rot,    // [FRAMES, 22, 6]
                const float* __restrict__ off,    // [22, 3]
                float* __restrict__ out)
{
    __shared__ float soff[66];
    if (threadIdx.x < 66) soff[threadIdx.x] = off[threadIdx.x];
    __syncthreads();

    int fid = blockIdx.x * TPB + threadIdx.x;
    const float4* R = (const float4*)(rot  + (size_t)fid * 132);  // 33 vec4 per frame
    const float4* P = (const float4*)(pred + (size_t)fid * 60);   // 15 vec4 per frame

    #define OFF3(i) mk3(soff[3*(i)], soff[3*(i)+1], soff[3*(i)+2])

    float acc = 0.f;

    // ================= chain C trunk: 3 -> 6 -> 9 (longest dep chain, start first)
    M3 G9;
    V3 pos9;
    {
        float4 q4  = __ldg(R+4),  q5  = __ldg(R+5);
        float4 q9  = __ldg(R+9),  q10 = __ldg(R+10);
        float4 q13 = __ldg(R+13), q14 = __ldg(R+14);

        M3 G3 = convB(q4, q5);                       // joint 3
        V3 pos3 = OFF3(3);
        {   float4 p0 = __ldg(P+0), p1 = __ldg(P+1), p3 = __ldg(P+3), p5 = __ldg(P+5);
            acc += dst(mk3(p0.w, p1.x, p1.y), pos3);                 // k=1
            M3 G6 = matmul(G3, convA(q9, q10));      // joint 6
            V3 pos6 = v_add(pos3, matvec(G3, OFF3(6)));
            acc += dst(mk3(p3.x, p3.y, p3.z), pos6);                 // k=4
            G9 = matmul(G6, convB(q13, q14));        // joint 9
            pos9 = v_add(pos6, matvec(G6, OFF3(9)));
            acc += dst(mk3(p5.y, p5.z, p5.w), pos9);                 // k=7
        }
    }

    // ================= chain A: 1(identity) -> 4 -> 7 -> 10
    {
        float4 q6  = __ldg(R+6),  q7  = __ldg(R+7);
        float4 q10 = __ldg(R+10), q11 = __ldg(R+11);

        M3 G4 = convA(q6, q7);                       // joint 4
        V3 pos4 = v_add(OFF3(1), OFF3(4));
        float4 p1 = __ldg(P+1), p2 = __ldg(P+2);
        acc += dst(mk3(p1.z, p1.w, p2.x), pos4);                     // k=2
        M3 G7 = matmul(G4, convB(q10, q11));         // joint 7
        V3 pos7 = v_add(pos4, matvec(G4, OFF3(7)));
        float4 p3 = __ldg(P+3), p4 = __ldg(P+4);
        acc += dst(mk3(p3.w, p4.x, p4.y), pos7);                     // k=5
        V3 pos10 = v_add(pos7, matvec(G7, OFF3(10)));
        float4 p6 = __ldg(P+6);
        acc += dst(mk3(p6.x, p6.y, p6.z), pos10);                    // k=8
    }

    // ================= chain B: 2 -> 5 -> 8 -> 11
    {
        float4 q3  = __ldg(R+3),  q4  = __ldg(R+4);
        float4 q7  = __ldg(R+7),  q8  = __ldg(R+8);
        float4 q12 = __ldg(R+12), q13 = __ldg(R+13);

        M3 G2 = convA(q3, q4);                       // joint 2
        V3 pos2 = OFF3(2);
        float4 p0 = __ldg(P+0);
        acc += dst(mk3(p0.x, p0.y, p0.z), pos2);                     // k=0
        M3 G5 = matmul(G2, convB(q7, q8));           // joint 5
        V3 pos5 = v_add(pos2, matvec(G2, OFF3(5)));
        float4 p2 = __ldg(P+2);
        acc += dst(mk3(p2.y, p2.z, p2.w), pos5);                     // k=3
        M3 G8 = matmul(G5, convA(q12, q13));         // joint 8
        V3 pos8 = v_add(pos5, matvec(G5, OFF3(8)));
        float4 p4 = __ldg(P+4), p5 = __ldg(P+5);
        acc += dst(mk3(p4.z, p4.w, p5.x), pos8);                     // k=6
        V3 pos11 = v_add(pos8, matvec(G8, OFF3(11)));
        float4 p6 = __ldg(P+6), p7 = __ldg(P+7);
        acc += dst(mk3(p6.w, p7.x, p7.y), pos11);                    // k=9
    }

    // ================= branch 12 -> 15
    {
        float4 q18 = __ldg(R+18), q19 = __ldg(R+19);
        M3 G12 = matmul(G9, convA(q18, q19));        // joint 12
        V3 pos12 = v_add(pos9, matvec(G9, OFF3(12)));
        float4 p7 = __ldg(P+7), p8 = __ldg(P+8);
        acc += dst(mk3(p7.z, p7.w, p8.x), pos12);                    // k=10
        V3 pos15 = v_add(pos12, matvec(G12, OFF3(15)));
        float4 p9 = __ldg(P+9), p10 = __ldg(P+10);
        acc += dst(mk3(p9.w, p10.x, p10.y), pos15);                  // k=13
    }

    // ================= branch 13 -> 16 -> 18 -> 20
    {
        float4 q19 = __ldg(R+19), q20 = __ldg(R+20);
        float4 q24 = __ldg(R+24), q25 = __ldg(R+25);
        float4 q27 = __ldg(R+27), q28 = __ldg(R+28);

        M3 G13 = matmul(G9, convB(q19, q20));        // joint 13
        V3 pos13 = v_add(pos9, matvec(G9, OFF3(13)));
        float4 p8 = __ldg(P+8);
        acc += dst(mk3(p8.y, p8.z, p8.w), pos13);                    // k=11
        M3 G16 = matmul(G13, convA(q24, q25));       // joint 16
        V3 pos16 = v_add(pos13, matvec(G13, OFF3(16)));
        float4 p10 = __ldg(P+10), p11 = __ldg(P+11);
        acc += dst(mk3(p10.z, p10.w, p11.x), pos16);                 // k=14
        M3 G18 = matmul(G16, convA(q27, q28));       // joint 18
        V3 pos18 = v_add(pos16, matvec(G16, OFF3(18)));
        float4 p12 = __ldg(P+12);
        acc += dst(mk3(p12.x, p12.y, p12.z), pos18);                 // k=16
        V3 pos20 = v_add(pos18, matvec(G18, OFF3(20)));
        float4 p13 = __ldg(P+13), p14 = __ldg(P+14);
        acc += dst(mk3(p13.z, p13.w, p14.x), pos20);                 // k=18
    }

    // ================= branch 14 -> 17 -> 19 -> 21
    {
        float4 q21 = __ldg(R+21), q22 = __ldg(R+22);
        float4 q25 = __ldg(R+25), q26 = __ldg(R+26);
        float4 q28 = __ldg(R+28), q29 = __ldg(R+29);

        M3 G14 = matmul(G9, convA(q21, q22));        // joint 14
        V3 pos14 = v_add(pos9, matvec(G9, OFF3(14)));
        float4 p9 = __ldg(P+9);
        acc += dst(mk3(p9.x, p9.y, p9.z), pos14);                    // k=12
        M3 G17 = matmul(G14, convB(q25, q26));       // joint 17
        V3 pos17 = v_add(pos14, matvec(G14, OFF3(17)));
        float4 p11 = __ldg(P+11);
        acc += dst(mk3(p11.y, p11.z, p11.w), pos17);                 // k=15
        M3 G19 = matmul(G17, convB(q28, q29));       // joint 19
        V3 pos19 = v_add(pos17, matvec(G17, OFF3(19)));
        float4 p13 = __ldg(P+13), p14 = __ldg(P+14);
        acc += dst(mk3(p13.w, p14.x, p14.y), pos19);                 // k=17
        V3 pos21 = v_add(pos19, matvec(G19, OFF3(21)));
        acc += dst(mk3(p14.y, p14.z, p14.w), pos21);                 // k=19
    }

    #undef OFF3

    // ---- deterministic block reduction ----
    #pragma unroll
    for (int o = 16; o > 0; o >>= 1)
        acc += __shfl_down_sync(0xffffffffu, acc, o);

    __shared__ float wsum[TPB / 32];
    int lane = threadIdx.x & 31, wid = threadIdx.x >> 5;
    if (lane == 0) wsum[wid] = acc;
    __syncthreads();

    __shared__ bool is_last;
    if (threadIdx.x == 0) {
        float s = 0.f;
        #pragma unroll
        for (int i = 0; i < TPB / 32; i++) s += wsum[i];
        g_partial[blockIdx.x] = s;
        __threadfence();
        unsigned prev = atomicAdd(&g_count, 1u);
        is_last = (prev == NBLK - 1);
    }
    __syncthreads();

    // ---- last block folds all partials (fixed order -> deterministic) ----
    if (is_last) {
        int t = threadIdx.x;
        float s = 0.f;
        #pragma unroll
        for (int j = 0; j < NBLK / TPB; j++) {
            const float* addr = g_partial + t + j * TPB;
            float v;
            asm volatile("ld.global.cg.f32 %0, [%1];" : "=f"(v) : "l"(addr));
            s += v;
        }
        __shared__ float sh[TPB];
        sh[t] = s;
        __syncthreads();
        #pragma unroll
        for (int k = TPB / 2; k > 0; k >>= 1) {
            if (t < k) sh[t] += sh[t + k];
            __syncthreads();
        }
        if (t == 0) {
            out[0] = sh[0] * (1000.0f / (float)(FRAMES * 20));
            g_count = 0;   // reset for next graph replay
        }
    }
}

extern "C" void kernel_launch(void* const* d_in, const int* in_sizes, int n_in,
                              void* d_out, int out_size) {
    const float* pred = (const float*)d_in[0];   // pred_pos [32,4096,20,3]
    const float* rot  = (const float*)d_in[1];   // gt_rot   [32,4096,22,6]
    const float* off  = (const float*)d_in[2];   // offsets  [22,3]
    float* out = (float*)d_out;

    fk_mpjpe_kernel<<<NBLK, TPB>>>(pred, rot, off, out);
}

// round 4
// speedup vs baseline: 1.4451x; 1.1599x over previous
#include <cuda_runtime.h>

// Problem constants (B=32, S=4096, 22 joints, 20 output joints)
#define FRAMES   (32 * 4096)
#define TPB      128
#define NBLK     (FRAMES / TPB)   // 1024

__device__ float    g_partial[NBLK];
__device__ unsigned g_count = 0;

struct V3 { float x, y, z; };
struct M3 { V3 c0, c1, c2; };   // columns

__device__ __forceinline__ V3 mk3(float x, float y, float z) { V3 v; v.x=x; v.y=y; v.z=z; return v; }
__device__ __forceinline__ V3 v_add(V3 a, V3 b) { return mk3(a.x+b.x, a.y+b.y, a.z+b.z); }

__device__ __forceinline__ V3 matvec(const M3& m, V3 v) {
    return mk3(fmaf(m.c0.x, v.x, fmaf(m.c1.x, v.y, m.c2.x * v.z)),
               fmaf(m.c0.y, v.x, fmaf(m.c1.y, v.y, m.c2.y * v.z)),
               fmaf(m.c0.z, v.x, fmaf(m.c1.z, v.y, m.c2.z * v.z)));
}
__device__ __forceinline__ M3 matmul(const M3& a, const M3& b) {
    M3 r; r.c0 = matvec(a, b.c0); r.c1 = matvec(a, b.c1); r.c2 = matvec(a, b.c2); return r;
}

// 6D continuous rotation rep -> 3x3 matrix (columns b1,b2,b3).
__device__ __forceinline__ M3 conv6d(V3 a1, V3 a2) {
    float n1 = fmaf(a1.x, a1.x, fmaf(a1.y, a1.y, a1.z * a1.z));
    float i1 = rsqrtf(fmaxf(n1, 1e-24f));
    V3 b1 = mk3(a1.x * i1, a1.y * i1, a1.z * i1);

    float dp = fmaf(b1.x, a2.x, fmaf(b1.y, a2.y, b1.z * a2.z));
    V3 t = mk3(fmaf(-dp, b1.x, a2.x), fmaf(-dp, b1.y, a2.y), fmaf(-dp, b1.z, a2.z));
    float n2 = fmaf(t.x, t.x, fmaf(t.y, t.y, t.z * t.z));
    float i2 = rsqrtf(fmaxf(n2, 1e-24f));
    V3 b2 = mk3(t.x * i2, t.y * i2, t.z * i2);

    V3 b3 = mk3(b1.y * b2.z - b1.z * b2.y,
                b1.z * b2.x - b1.x * b2.z,
                b1.x * b2.y - b1.y * b2.x);
    M3 m; m.c0 = b1; m.c1 = b2; m.c2 = b3; return m;
}

// two alignment forms of a 6-float span inside consecutive float4s
__device__ __forceinline__ M3 convA(float4 p, float4 q) {   // span starts at comp 0
    return conv6d(mk3(p.x, p.y, p.z), mk3(p.w, q.x, q.y));
}
__device__ __forceinline__ M3 convB(float4 p, float4 q) {   // span starts at comp 2
    return conv6d(mk3(p.z, p.w, q.x), mk3(q.y, q.z, q.w));
}

__device__ __forceinline__ float dst(V3 p, V3 g) {
    float dx = p.x - g.x, dy = p.y - g.y, dz = p.z - g.z;
    return sqrtf(fmaf(dx, dx, fmaf(dy, dy, dz * dz)));
}

__global__ void __launch_bounds__(TPB)
fk_mpjpe_kernel(const float* __restrict__ pred,   // [FRAMES, 20, 3]
                const float* __restrict__ rot,    // [FRAMES, 22, 6]
                const float* __restrict__ off,    // [22, 3]
                float* __restrict__ out)
{
    // rows padded (13 / 9 float4) -> conflict-free LDS.128 per quarter-warp
    __shared__ float4 srot [TPB * 13];   // 12 rot words per frame + pad
    __shared__ float4 spred[TPB * 9];    //  8 pred words per frame + pad
    __shared__ float  soff[66];
    __shared__ float  wsum[TPB / 32];
    __shared__ bool   is_last;

    const int tid = threadIdx.x;
    const size_t f0 = (size_t)blockIdx.x * TPB;
    const float4* Rg = (const float4*)rot  + f0 * 33;
    const float4* Pg = (const float4*)pred + f0 * 15;

    if (tid < 66) soff[tid] = off[tid];

    // ================= PHASE 1 staging: rot words 3..14, pred words 0..7 (coalesced)
    #pragma unroll
    for (int j = 0; j < 12; j++) {
        unsigned i = tid + j * TPB;
        unsigned fr = i / 12u, w = i % 12u;
        srot[fr * 13 + w] = __ldg(Rg + fr * 33 + 3 + w);
    }
    #pragma unroll
    for (int j = 0; j < 8; j++) {
        unsigned i = tid + j * TPB;
        unsigned fr = i >> 3, w = i & 7u;
        spred[fr * 9 + w] = __ldg(Pg + fr * 15 + w);
    }
    __syncthreads();

    const float4* q = srot  + tid * 13 - 3;   // q[w] valid for w = 3..14
    const float4* P = spred + tid * 9;        // P[w] valid for w = 0..7

    #define OFF3(i) mk3(soff[3*(i)], soff[3*(i)+1], soff[3*(i)+2])

    float acc = 0.f;
    M3 G9; V3 pos9;

    // ---- chain: 3 -> 6 -> 9 (trunk; G9/pos9 carried to phase 2) ----
    {
        M3 G3 = convB(q[4], q[5]);
        V3 pos3 = OFF3(3);
        float4 p0 = P[0], p1 = P[1];
        acc += dst(mk3(p0.w, p1.x, p1.y), pos3);                  // k=1
        M3 G6 = matmul(G3, convA(q[9], q[10]));
        V3 pos6 = v_add(pos3, matvec(G3, OFF3(6)));
        float4 p3 = P[3];
        acc += dst(mk3(p3.x, p3.y, p3.z), pos6);                  // k=4
        G9 = matmul(G6, convB(q[13], q[14]));
        pos9 = v_add(pos6, matvec(G6, OFF3(9)));
        float4 p5 = P[5];
        acc += dst(mk3(p5.y, p5.z, p5.w), pos9);                  // k=7
    }

    // ---- chain: 1(identity) -> 4 -> 7 -> 10 ----
    {
        M3 G4 = convA(q[6], q[7]);
        V3 pos4 = v_add(OFF3(1), OFF3(4));
        float4 p1 = P[1], p2 = P[2];
        acc += dst(mk3(p1.z, p1.w, p2.x), pos4);                  // k=2
        M3 G7 = matmul(G4, convB(q[10], q[11]));
        V3 pos7 = v_add(pos4, matvec(G4, OFF3(7)));
        float4 p3 = P[3], p4 = P[4];
        acc += dst(mk3(p3.w, p4.x, p4.y), pos7);                  // k=5
        V3 pos10 = v_add(pos7, matvec(G7, OFF3(10)));
        float4 p6 = P[6];
        acc += dst(mk3(p6.x, p6.y, p6.z), pos10);                 // k=8
    }

    // ---- chain: 2 -> 5 -> 8 -> 11 ----
    {
        M3 G2 = convA(q[3], q[4]);
        V3 pos2 = OFF3(2);
        float4 p0 = P[0];
        acc += dst(mk3(p0.x, p0.y, p0.z), pos2);                  // k=0
        M3 G5 = matmul(G2, convB(q[7], q[8]));
        V3 pos5 = v_add(pos2, matvec(G2, OFF3(5)));
        float4 p2 = P[2];
        acc += dst(mk3(p2.y, p2.z, p2.w), pos5);                  // k=3
        M3 G8 = matmul(G5, convA(q[12], q[13]));
        V3 pos8 = v_add(pos5, matvec(G5, OFF3(8)));
        float4 p4 = P[4], p5 = P[5];
        acc += dst(mk3(p4.z, p4.w, p5.x), pos8);                  // k=6
        V3 pos11 = v_add(pos8, matvec(G8, OFF3(11)));
        float4 p6 = P[6], p7 = P[7];
        acc += dst(mk3(p6.w, p7.x, p7.y), pos11);                 // k=9
    }

    // ================= PHASE 2 staging: rot words 18..29, pred words 7..14
    __syncthreads();   // all phase-1 smem reads done
    #pragma unroll
    for (int j = 0; j < 12; j++) {
        unsigned i = tid + j * TPB;
        unsigned fr = i / 12u, w = i % 12u;
        srot[fr * 13 + w] = __ldg(Rg + fr * 33 + 18 + w);
    }
    #pragma unroll
    for (int j = 0; j < 8; j++) {
        unsigned i = tid + j * TPB;
        unsigned fr = i >> 3, w = i & 7u;
        spred[fr * 9 + w] = __ldg(Pg + fr * 15 + 7 + w);
    }
    __syncthreads();

    const float4* r2 = srot  + tid * 13 - 18;  // r2[w] valid for w = 18..29
    const float4* P2 = spred + tid * 9 - 7;    // P2[w] valid for w = 7..14

    // ---- branch 12 -> 15 ----
    {
        M3 G12 = matmul(G9, convA(r2[18], r2[19]));
        V3 pos12 = v_add(pos9, matvec(G9, OFF3(12)));
        float4 p7 = P2[7], p8 = P2[8];
        acc += dst(mk3(p7.z, p7.w, p8.x), pos12);                 // k=10
        V3 pos15 = v_add(pos12, matvec(G12, OFF3(15)));
        float4 p9 = P2[9], p10 = P2[10];
        acc += dst(mk3(p9.w, p10.x, p10.y), pos15);               // k=13
    }

    // ---- branch 13 -> 16 -> 18 -> 20 ----
    {
        M3 G13 = matmul(G9, convB(r2[19], r2[20]));
        V3 pos13 = v_add(pos9, matvec(G9, OFF3(13)));
        float4 p8 = P2[8];
        acc += dst(mk3(p8.y, p8.z, p8.w), pos13);                 // k=11
        M3 G16 = matmul(G13, convA(r2[24], r2[25]));
        V3 pos16 = v_add(pos13, matvec(G13, OFF3(16)));
        float4 p10 = P2[10], p11 = P2[11];
        acc += dst(mk3(p10.z, p10.w, p11.x), pos16);              // k=14
        M3 G18 = matmul(G16, convA(r2[27], r2[28]));
        V3 pos18 = v_add(pos16, matvec(G16, OFF3(18)));
        float4 p12 = P2[12];
        acc += dst(mk3(p12.x, p12.y, p12.z), pos18);              // k=16
        V3 pos20 = v_add(pos18, matvec(G18, OFF3(20)));
        float4 p13 = P2[13], p14 = P2[14];
        acc += dst(mk3(p13.z, p13.w, p14.x), pos20);              // k=18
    }

    // ---- branch 14 -> 17 -> 19 -> 21 ----
    {
        M3 G14 = matmul(G9, convA(r2[21], r2[22]));
        V3 pos14 = v_add(pos9, matvec(G9, OFF3(14)));
        float4 p9 = P2[9];
        acc += dst(mk3(p9.x, p9.y, p9.z), pos14);                 // k=12
        M3 G17 = matmul(G14, convB(r2[25], r2[26]));
        V3 pos17 = v_add(pos14, matvec(G14, OFF3(17)));
        float4 p11 = P2[11];
        acc += dst(mk3(p11.y, p11.z, p11.w), pos17);              // k=15
        M3 G19 = matmul(G17, convB(r2[28], r2[29]));
        V3 pos19 = v_add(pos17, matvec(G17, OFF3(19)));
        float4 p12 = P2[12], p13 = P2[13];
        acc += dst(mk3(p12.w, p13.x, p13.y), pos19);              // k=17 (FIXED mapping)
        V3 pos21 = v_add(pos19, matvec(G19, OFF3(21)));
        float4 p14 = P2[14];
        acc += dst(mk3(p14.y, p14.z, p14.w), pos21);              // k=19
    }

    #undef OFF3

    // ---- deterministic block reduction ----
    #pragma unroll
    for (int o = 16; o > 0; o >>= 1)
        acc += __shfl_down_sync(0xffffffffu, acc, o);

    int lane = tid & 31, wid = tid >> 5;
    if (lane == 0) wsum[wid] = acc;
    __syncthreads();

    if (tid == 0) {
        float s = 0.f;
        #pragma unroll
        for (int i = 0; i < TPB / 32; i++) s += wsum[i];
        g_partial[blockIdx.x] = s;
        __threadfence();
        unsigned prev = atomicAdd(&g_count, 1u);
        is_last = (prev == NBLK - 1);
    }
    __syncthreads();

    // ---- last block folds all partials (fixed order -> deterministic) ----
    if (is_last) {
        float s = 0.f;
        #pragma unroll
        for (int j = 0; j < NBLK / TPB; j++) {
            const float* addr = g_partial + tid + j * TPB;
            float v;
            asm volatile("ld.global.cg.f32 %0, [%1];" : "=f"(v) : "l"(addr));
            s += v;
        }
        __shared__ float sh[TPB];
        sh[tid] = s;
        __syncthreads();
        #pragma unroll
        for (int k = TPB / 2; k > 0; k >>= 1) {
            if (tid < k) sh[tid] += sh[tid + k];
            __syncthreads();
        }
        if (tid == 0) {
            out[0] = sh[0] * (1000.0f / (float)(FRAMES * 20));
            g_count = 0;   // reset for next graph replay
        }
    }
}

extern "C" void kernel_launch(void* const* d_in, const int* in_sizes, int n_in,
                              void* d_out, int out_size) {
    const float* pred = (const float*)d_in[0];   // pred_pos [32,4096,20,3]
    const float* rot  = (const float*)d_in[1];   // gt_rot   [32,4096,22,6]
    const float* off  = (const float*)d_in[2];   // offsets  [22,3]
    float* out = (float*)d_out;

    fk_mpjpe_kernel<<<NBLK, TPB>>>(pred, rot, off, out);
}